// round 4
// baseline (speedup 1.0000x reference)
#include <cuda_runtime.h>
#include <cstdint>

#define VOCAB 128
#define NTAGS 8
#define EDIM  256
#define HDIM  1024
#define BATCH 1024
#define SEQ   128

// ------------------------- device scratch (static, no allocs) -------------
__device__ float g_Q[VOCAB * HDIM];                       // 512 KB, L2-resident
__device__ int   g_len[BATCH];
__device__ float g_H[(size_t)SEQ * BATCH * HDIM];         // 512 MB: h after step t

// ===========================================================================
// Q[v][h] = sum_e emb[v][e] * W_ih[h][e] + b_ih[h] + b_hh[h]
// grid = VOCAB blocks, 256 threads (8 warps), warp-per-h row
// ===========================================================================
__global__ void q_kernel(const float* __restrict__ emb,
                         const float* __restrict__ W_ih,
                         const float* __restrict__ b_ih,
                         const float* __restrict__ b_hh) {
    int v = blockIdx.x;
    int warp = threadIdx.x >> 5, lane = threadIdx.x & 31;
    const float* e = emb + v * EDIM;
    for (int h = warp; h < HDIM; h += 8) {
        const float* w = W_ih + h * EDIM;
        float acc = 0.f;
        #pragma unroll
        for (int k = lane; k < EDIM; k += 32) acc += e[k] * w[k];
        #pragma unroll
        for (int o = 16; o > 0; o >>= 1) acc += __shfl_down_sync(0xffffffffu, acc, o);
        if (lane == 0) g_Q[v * HDIM + h] = acc + b_ih[h] + b_hh[h];
    }
}

// ===========================================================================
// seq_lengths + t=0 step (h0 = 0 so pre-activation is just Q[id0])
// grid = BATCH blocks, 128 threads
// ===========================================================================
__global__ void t0_kernel(const int* __restrict__ ids) {
    int b = blockIdx.x, tid = threadIdx.x;
    int m = (ids[b * SEQ + tid] != 0) ? 1 : 0;
    __shared__ int ws[4];
    #pragma unroll
    for (int o = 16; o > 0; o >>= 1) m += __shfl_down_sync(0xffffffffu, m, o);
    if ((tid & 31) == 0) ws[tid >> 5] = m;
    __syncthreads();
    int len = ws[0] + ws[1] + ws[2] + ws[3];
    if (tid == 0) g_len[b] = len;

    int id0 = ids[b * SEQ];
    const float* q = g_Q + (size_t)id0 * HDIM;
    float* hout = g_H + (size_t)b * HDIM;      // t=0 slice
    for (int h = tid; h < HDIM; h += 128)
        hout[h] = (len > 0) ? tanhf(q[h]) : 0.f;
}

// ===========================================================================
// Step t (t>=1): Hout[b][n] = mask ? tanh(Q[id[b,t]][n] + sum_k Hprev[b][k]*W_hh[n][k])
//                                  : Hprev[b][n]
// tf32 mma.sync m16n8k8. CTA tile 128(M) x 64(N), K-chunk 16, double buffer.
// 8 warps: warp (wm = w&3 -> M, wn = w>>2 -> N), warp tile 32x32.
// grid = dim3(HDIM/64, BATCH/128) = (16, 8) = 128 CTAs, 256 threads.
// ===========================================================================
#define KCH   16
#define APAD  20                       // (20*g + c) % 32 distinct for g<8,c<4
#define SMA   (128 * APAD)
#define SMB   (64 * APAD)

__device__ __forceinline__ void mma_tf32(float* d, const uint32_t* a, const uint32_t* b) {
    asm volatile(
        "mma.sync.aligned.m16n8k8.row.col.f32.tf32.tf32.f32 "
        "{%0,%1,%2,%3}, {%4,%5,%6,%7}, {%8,%9}, {%0,%1,%2,%3};\n"
        : "+f"(d[0]), "+f"(d[1]), "+f"(d[2]), "+f"(d[3])
        : "r"(a[0]), "r"(a[1]), "r"(a[2]), "r"(a[3]), "r"(b[0]), "r"(b[1]));
}

__global__ void __launch_bounds__(256, 1)
step_kernel(const float* __restrict__ W_hh, const int* __restrict__ ids, int t) {
    __shared__ float As[2][SMA];
    __shared__ float Bs[2][SMB];

    const float* __restrict__ Hprev = g_H + (size_t)(t - 1) * BATCH * HDIM;
    float* __restrict__ Hout        = g_H + (size_t)t       * BATCH * HDIM;

    const int tid  = threadIdx.x;
    const int lane = tid & 31, warp = tid >> 5;
    const int wm = warp & 3, wn = warp >> 2;
    const int g  = lane >> 2, c = lane & 3;
    const int m0 = blockIdx.y * 128;
    const int n0 = blockIdx.x * 64;

    float acc[2][4][4] = {};

    // --- async tile loaders (KCH=16: A = 512 float4, B = 256 float4) -------
    #define LD_A(stage, k0)                                                          \
        do {                                                                         \
            _Pragma("unroll")                                                        \
            for (int i = 0; i < 2; i++) {                                            \
                int idx = tid + i * 256;                                             \
                int r = idx >> 2, c4 = idx & 3;                                      \
                const float* gp = Hprev + (size_t)(m0 + r) * HDIM + (k0) + c4 * 4;   \
                uint32_t sp = (uint32_t)__cvta_generic_to_shared(                    \
                    &As[stage][r * APAD + c4 * 4]);                                  \
                asm volatile("cp.async.cg.shared.global [%0], [%1], 16;\n"           \
                             :: "r"(sp), "l"(gp));                                   \
            }                                                                        \
        } while (0)
    #define LD_B(stage, k0)                                                          \
        do {                                                                         \
            int r = tid >> 2, c4 = tid & 3;                                          \
            const float* gp = W_hh + (size_t)(n0 + r) * HDIM + (k0) + c4 * 4;        \
            uint32_t sp = (uint32_t)__cvta_generic_to_shared(                        \
                &Bs[stage][r * APAD + c4 * 4]);                                      \
            asm volatile("cp.async.cg.shared.global [%0], [%1], 16;\n"               \
                         :: "r"(sp), "l"(gp));                                       \
        } while (0)

    LD_A(0, 0); LD_B(0, 0);
    asm volatile("cp.async.commit_group;\n");

    const int NCH = HDIM / KCH;   // 64
    for (int ch = 0; ch < NCH; ch++) {
        const int buf = ch & 1;
        if (ch + 1 < NCH) {
            LD_A(buf ^ 1, (ch + 1) * KCH);
            LD_B(buf ^ 1, (ch + 1) * KCH);
            asm volatile("cp.async.commit_group;\n");
            asm volatile("cp.async.wait_group 1;\n");
        } else {
            asm volatile("cp.async.wait_group 0;\n");
        }
        __syncthreads();

        const float* A  = &As[buf][(wm * 32) * APAD];
        const float* Bp = &Bs[buf][(wn * 32) * APAD];
        #pragma unroll
        for (int ks = 0; ks < KCH / 8; ks++) {
            uint32_t a[2][4], bb[4][2];
            #pragma unroll
            for (int mt = 0; mt < 2; mt++) {
                const float* ap = A + (mt * 16 + g) * APAD + ks * 8 + c;
                a[mt][0] = __float_as_uint(ap[0]);
                a[mt][1] = __float_as_uint(ap[8 * APAD]);
                a[mt][2] = __float_as_uint(ap[4]);
                a[mt][3] = __float_as_uint(ap[8 * APAD + 4]);
            }
            #pragma unroll
            for (int nt = 0; nt < 4; nt++) {
                const float* bp = Bp + (nt * 8 + g) * APAD + ks * 8 + c;
                bb[nt][0] = __float_as_uint(bp[0]);
                bb[nt][1] = __float_as_uint(bp[4]);
            }
            #pragma unroll
            for (int mt = 0; mt < 2; mt++)
                #pragma unroll
                for (int nt = 0; nt < 4; nt++)
                    mma_tf32(acc[mt][nt], a[mt], bb[nt]);
        }
        __syncthreads();
    }

    // --- epilogue: + Q gather, tanh, mask --------------------------------
    const int c2 = c * 2;
    #pragma unroll
    for (int mt = 0; mt < 2; mt++) {
        const int r0 = m0 + wm * 32 + mt * 16 + g;
        const int r1 = r0 + 8;
        const int id0 = ids[r0 * SEQ + t];
        const int id1 = ids[r1 * SEQ + t];
        const bool mk0 = t < g_len[r0];
        const bool mk1 = t < g_len[r1];
        const float* q0 = g_Q + (size_t)id0 * HDIM;
        const float* q1 = g_Q + (size_t)id1 * HDIM;
        float* o0 = Hout + (size_t)r0 * HDIM;
        float* o1 = Hout + (size_t)r1 * HDIM;
        const float* p0 = Hprev + (size_t)r0 * HDIM;
        const float* p1 = Hprev + (size_t)r1 * HDIM;
        #pragma unroll
        for (int nt = 0; nt < 4; nt++) {
            const int n = n0 + wn * 32 + nt * 8 + c2;
            o0[n]     = mk0 ? tanhf(acc[mt][nt][0] + q0[n])     : p0[n];
            o0[n + 1] = mk0 ? tanhf(acc[mt][nt][1] + q0[n + 1]) : p0[n + 1];
            o1[n]     = mk1 ? tanhf(acc[mt][nt][2] + q1[n])     : p1[n];
            o1[n + 1] = mk1 ? tanhf(acc[mt][nt][3] + q1[n + 1]) : p1[n + 1];
        }
    }
    #undef LD_A
    #undef LD_B
}

// ===========================================================================
// y[b][t][tag] = H[t][b][:] . W_out[tag][:] + b_out[tag]
// thread-per-(b,t) row, W_out broadcast from smem (conflict-free LDS.128).
// grid = B*T/256 = 512 blocks, 256 threads.
// ===========================================================================
__global__ void y_kernel(const float* __restrict__ W_out,
                         const float* __restrict__ b_out,
                         float* __restrict__ y) {
    __shared__ float sW[NTAGS * HDIM];   // 32 KB
    __shared__ float sb[NTAGS];
    for (int i = threadIdx.x; i < NTAGS * HDIM; i += 256) sW[i] = W_out[i];
    if (threadIdx.x < NTAGS) sb[threadIdx.x] = b_out[threadIdx.x];
    __syncthreads();

    const int r = blockIdx.x * 256 + threadIdx.x;   // r = b*SEQ + t
    const int b = r / SEQ, t = r % SEQ;
    const float4* h = (const float4*)(g_H + (size_t)t * BATCH * HDIM + (size_t)b * HDIM);

    float acc[NTAGS];
    #pragma unroll
    for (int tg = 0; tg < NTAGS; tg++) acc[tg] = sb[tg];

    #pragma unroll 4
    for (int k4 = 0; k4 < HDIM / 4; k4++) {
        const float4 hv = h[k4];
        #pragma unroll
        for (int tg = 0; tg < NTAGS; tg++) {
            const float4 wv = ((const float4*)(sW + tg * HDIM))[k4];
            acc[tg] += hv.x * wv.x + hv.y * wv.y + hv.z * wv.z + hv.w * wv.w;
        }
    }
    #pragma unroll
    for (int tg = 0; tg < NTAGS; tg++) y[(size_t)r * NTAGS + tg] = acc[tg];
}

// ===========================================================================
extern "C" void kernel_launch(void* const* d_in, const int* in_sizes, int n_in,
                              void* d_out, int out_size) {
    (void)in_sizes; (void)n_in; (void)out_size;
    const int*   ids   = (const int*)  d_in[0];
    const float* emb   = (const float*)d_in[1];
    const float* W_ih  = (const float*)d_in[2];
    const float* W_hh  = (const float*)d_in[3];
    const float* b_ih  = (const float*)d_in[4];
    const float* b_hh  = (const float*)d_in[5];
    const float* W_out = (const float*)d_in[6];
    const float* b_out = (const float*)d_in[7];
    float* y = (float*)d_out;

    q_kernel<<<VOCAB, 256>>>(emb, W_ih, b_ih, b_hh);
    t0_kernel<<<BATCH, 128>>>(ids);
    for (int t = 1; t < SEQ; t++)
        step_kernel<<<dim3(HDIM / 64, BATCH / 128), 256>>>(W_hh, ids, t);
    y_kernel<<<(BATCH * SEQ) / 256, 256>>>(W_out, b_out, y);
}

// round 5
// speedup vs baseline: 1.1922x; 1.1922x over previous
#include <cuda_runtime.h>
#include <cstdint>

#define VOCAB 128
#define NTAGS 8
#define EDIM  256
#define HDIM  1024
#define BATCH 1024
#define SEQ   128

// ------------------------- device scratch (static, no allocs) -------------
__device__ float g_Q[VOCAB * HDIM];                       // 512 KB, L2-resident
__device__ int   g_len[BATCH];
__device__ float g_H[(size_t)SEQ * BATCH * HDIM];         // 512 MB: h after step t

// ===========================================================================
// Q[v][h] = sum_e emb[v][e] * W_ih[h][e] + b_ih[h] + b_hh[h]
// ===========================================================================
__global__ void q_kernel(const float* __restrict__ emb,
                         const float* __restrict__ W_ih,
                         const float* __restrict__ b_ih,
                         const float* __restrict__ b_hh) {
    int v = blockIdx.x;
    int warp = threadIdx.x >> 5, lane = threadIdx.x & 31;
    const float* e = emb + v * EDIM;
    for (int h = warp; h < HDIM; h += 8) {
        const float* w = W_ih + h * EDIM;
        float acc = 0.f;
        #pragma unroll
        for (int k = lane; k < EDIM; k += 32) acc += e[k] * w[k];
        #pragma unroll
        for (int o = 16; o > 0; o >>= 1) acc += __shfl_down_sync(0xffffffffu, acc, o);
        if (lane == 0) g_Q[v * HDIM + h] = acc + b_ih[h] + b_hh[h];
    }
}

// ===========================================================================
// seq_lengths + t=0 step (h0 = 0 so pre-activation is just Q[id0])
// ===========================================================================
__global__ void t0_kernel(const int* __restrict__ ids) {
    int b = blockIdx.x, tid = threadIdx.x;
    int m = (ids[b * SEQ + tid] != 0) ? 1 : 0;
    __shared__ int ws[4];
    #pragma unroll
    for (int o = 16; o > 0; o >>= 1) m += __shfl_down_sync(0xffffffffu, m, o);
    if ((tid & 31) == 0) ws[tid >> 5] = m;
    __syncthreads();
    int len = ws[0] + ws[1] + ws[2] + ws[3];
    if (tid == 0) g_len[b] = len;

    int id0 = ids[b * SEQ];
    const float* q = g_Q + (size_t)id0 * HDIM;
    float* hout = g_H + (size_t)b * HDIM;
    for (int h = tid; h < HDIM; h += 128)
        hout[h] = (len > 0) ? tanhf(q[h]) : 0.f;
}

// ===========================================================================
// Step t (t>=1): tf32 m16n8k8, CTA 128x64, warp 32x32 (4x2 warps).
// 3-stage cp.async pipeline, KCH=32, one barrier per chunk,
// register double-buffered fragments.
// grid = (16, 8) = 128 CTAs, 256 threads, 81 KB dynamic smem.
// ===========================================================================
#define KCH      32
#define SPITCH   36                       /* 36 ≡ 4 (mod 32): conflict-free */
#define A_FLOATS (128 * SPITCH)           /* 4608 */
#define B_FLOATS (64  * SPITCH)           /* 2304 */
#define STAGE_F  (A_FLOATS + B_FLOATS)    /* 6912 */
#define NSTAGE   3
#define NCH      (HDIM / KCH)             /* 32 */
#define STEP_SMEM (NSTAGE * STAGE_F * 4)  /* 82944 B */

__device__ __forceinline__ void cp16(float* sp, const float* gp) {
    uint32_t s = (uint32_t)__cvta_generic_to_shared(sp);
    asm volatile("cp.async.cg.shared.global [%0], [%1], 16;\n" :: "r"(s), "l"(gp));
}

__device__ __forceinline__ void mma_tf32(float* d, const uint32_t* a, const uint32_t* b) {
    asm volatile(
        "mma.sync.aligned.m16n8k8.row.col.f32.tf32.tf32.f32 "
        "{%0,%1,%2,%3}, {%4,%5,%6,%7}, {%8,%9}, {%0,%1,%2,%3};\n"
        : "+f"(d[0]), "+f"(d[1]), "+f"(d[2]), "+f"(d[3])
        : "r"(a[0]), "r"(a[1]), "r"(a[2]), "r"(a[3]), "r"(b[0]), "r"(b[1]));
}

extern __shared__ float smem_dyn[];

__global__ void __launch_bounds__(256, 1)
step_kernel(const float* __restrict__ W_hh, const int* __restrict__ ids, int t) {
    const float* __restrict__ Hprev = g_H + (size_t)(t - 1) * BATCH * HDIM;
    float* __restrict__ Hout        = g_H + (size_t)t       * BATCH * HDIM;

    const int tid  = threadIdx.x;
    const int lane = tid & 31, warp = tid >> 5;
    const int wm = warp & 3, wn = warp >> 2;
    const int g  = lane >> 2, c = lane & 3;
    const int m0 = blockIdx.y * 128;
    const int n0 = blockIdx.x * 64;

    // hoisted epilogue scalars (independent of GEMM)
    const int r0  = m0 + wm * 32 + g;      // row for mt=0 (and +8 / +16 / +24)
    const int e_r0 = r0,           e_r1 = r0 + 8;
    const int e_r2 = r0 + 16,      e_r3 = r0 + 24;
    const int id_a = ids[e_r0 * SEQ + t], id_b = ids[e_r1 * SEQ + t];
    const int id_c = ids[e_r2 * SEQ + t], id_d = ids[e_r3 * SEQ + t];
    const bool mka = t < g_len[e_r0], mkb = t < g_len[e_r1];
    const bool mkc = t < g_len[e_r2], mkd = t < g_len[e_r3];

    float acc[2][4][4] = {};

    // --- stage loader: A = 128x32 (4 cp16/thr), B = 64x32 (2 cp16/thr) -----
    #define LOAD_STAGE(st, k0)                                                     \
        do {                                                                       \
            float* base = smem_dyn + (st) * STAGE_F;                               \
            _Pragma("unroll")                                                      \
            for (int i = 0; i < 4; i++) {                                          \
                int idx = tid + i * 256;                                           \
                int r = idx >> 3, c8 = idx & 7;                                    \
                cp16(base + r * SPITCH + c8 * 4,                                   \
                     Hprev + (size_t)(m0 + r) * HDIM + (k0) + c8 * 4);             \
            }                                                                      \
            float* bb = base + A_FLOATS;                                           \
            _Pragma("unroll")                                                      \
            for (int i = 0; i < 2; i++) {                                          \
                int idx = tid + i * 256;                                           \
                int r = idx >> 3, c8 = idx & 7;                                    \
                cp16(bb + r * SPITCH + c8 * 4,                                     \
                     W_hh + (size_t)(n0 + r) * HDIM + (k0) + c8 * 4);              \
            }                                                                      \
            asm volatile("cp.async.commit_group;\n");                              \
        } while (0)

    #define LDFRAG(da, db, ksv)                                                    \
        do {                                                                       \
            _Pragma("unroll")                                                      \
            for (int mt = 0; mt < 2; mt++) {                                       \
                const float* ap = A + (mt * 16 + g) * SPITCH + (ksv) * 8 + c;      \
                da[mt][0] = __float_as_uint(ap[0]);                                \
                da[mt][1] = __float_as_uint(ap[8 * SPITCH]);                       \
                da[mt][2] = __float_as_uint(ap[4]);                                \
                da[mt][3] = __float_as_uint(ap[8 * SPITCH + 4]);                   \
            }                                                                      \
            _Pragma("unroll")                                                      \
            for (int nt = 0; nt < 4; nt++) {                                       \
                const float* bp = B + (nt * 8 + g) * SPITCH + (ksv) * 8 + c;       \
                db[nt][0] = __float_as_uint(bp[0]);                                \
                db[nt][1] = __float_as_uint(bp[4]);                                \
            }                                                                      \
        } while (0)

    LOAD_STAGE(0, 0);
    LOAD_STAGE(1, KCH);

    for (int ch = 0; ch < NCH; ch++) {
        if (ch == NCH - 1) asm volatile("cp.async.wait_group 0;\n");
        else               asm volatile("cp.async.wait_group 1;\n");
        __syncthreads();

        const int st = ch % NSTAGE;
        const float* A = smem_dyn + st * STAGE_F + (wm * 32) * SPITCH;
        const float* B = smem_dyn + st * STAGE_F + A_FLOATS + (wn * 32) * SPITCH;

        uint32_t af[2][2][4], bf[2][4][2];
        LDFRAG(af[0], bf[0], 0);
        #pragma unroll
        for (int ks = 0; ks < KCH / 8; ks++) {
            const int cur = ks & 1;
            if (ks < KCH / 8 - 1) LDFRAG(af[cur ^ 1], bf[cur ^ 1], ks + 1);
            #pragma unroll
            for (int mt = 0; mt < 2; mt++)
                #pragma unroll
                for (int nt = 0; nt < 4; nt++)
                    mma_tf32(acc[mt][nt], af[cur][mt], bf[cur][nt]);
        }
        // refill the stage freed at iteration ch-1 (barrier above protects it)
        if (ch + 2 < NCH) LOAD_STAGE((ch + 2) % NSTAGE, (ch + 2) * KCH);
    }

    // --- epilogue: + Q gather, tanh, mask --------------------------------
    const int c2 = c * 2;
    #pragma unroll
    for (int mt = 0; mt < 2; mt++) {
        const int rA = (mt == 0) ? e_r0 : e_r2;
        const int rB = (mt == 0) ? e_r1 : e_r3;
        const int idA = (mt == 0) ? id_a : id_c;
        const int idB = (mt == 0) ? id_b : id_d;
        const bool mA = (mt == 0) ? mka : mkc;
        const bool mB = (mt == 0) ? mkb : mkd;
        const float* q0 = g_Q + (size_t)idA * HDIM;
        const float* q1 = g_Q + (size_t)idB * HDIM;
        float* o0 = Hout + (size_t)rA * HDIM;
        float* o1 = Hout + (size_t)rB * HDIM;
        const float* p0 = Hprev + (size_t)rA * HDIM;
        const float* p1 = Hprev + (size_t)rB * HDIM;
        #pragma unroll
        for (int nt = 0; nt < 4; nt++) {
            const int n = n0 + wn * 32 + nt * 8 + c2;
            o0[n]     = mA ? tanhf(acc[mt][nt][0] + q0[n])     : p0[n];
            o0[n + 1] = mA ? tanhf(acc[mt][nt][1] + q0[n + 1]) : p0[n + 1];
            o1[n]     = mB ? tanhf(acc[mt][nt][2] + q1[n])     : p1[n];
            o1[n + 1] = mB ? tanhf(acc[mt][nt][3] + q1[n + 1]) : p1[n + 1];
        }
    }
    #undef LOAD_STAGE
    #undef LDFRAG
}

// NOTE on epilogue row mapping: warp tile rows are wm*32 + {mt*16 + g, +8}.
// mt=0 covers rows g, g+8 (e_r0, e_r1); mt=1 covers g+16, g+24 (e_r2, e_r3).

// ===========================================================================
// y[b][t][tag] = H[t][b][:] . W_out[tag][:] + b_out[tag]
// ===========================================================================
__global__ void y_kernel(const float* __restrict__ W_out,
                         const float* __restrict__ b_out,
                         float* __restrict__ y) {
    __shared__ float sW[NTAGS * HDIM];
    __shared__ float sb[NTAGS];
    for (int i = threadIdx.x; i < NTAGS * HDIM; i += 256) sW[i] = W_out[i];
    if (threadIdx.x < NTAGS) sb[threadIdx.x] = b_out[threadIdx.x];
    __syncthreads();

    const int r = blockIdx.x * 256 + threadIdx.x;   // r = b*SEQ + t
    const int b = r / SEQ, t = r % SEQ;
    const float4* h = (const float4*)(g_H + (size_t)t * BATCH * HDIM + (size_t)b * HDIM);

    float acc[NTAGS];
    #pragma unroll
    for (int tg = 0; tg < NTAGS; tg++) acc[tg] = sb[tg];

    #pragma unroll 4
    for (int k4 = 0; k4 < HDIM / 4; k4++) {
        const float4 hv = h[k4];
        #pragma unroll
        for (int tg = 0; tg < NTAGS; tg++) {
            const float4 wv = ((const float4*)(sW + tg * HDIM))[k4];
            acc[tg] += hv.x * wv.x + hv.y * wv.y + hv.z * wv.z + hv.w * wv.w;
        }
    }
    #pragma unroll
    for (int tg = 0; tg < NTAGS; tg++) y[(size_t)r * NTAGS + tg] = acc[tg];
}

// ===========================================================================
extern "C" void kernel_launch(void* const* d_in, const int* in_sizes, int n_in,
                              void* d_out, int out_size) {
    (void)in_sizes; (void)n_in; (void)out_size;
    const int*   ids   = (const int*)  d_in[0];
    const float* emb   = (const float*)d_in[1];
    const float* W_ih  = (const float*)d_in[2];
    const float* W_hh  = (const float*)d_in[3];
    const float* b_ih  = (const float*)d_in[4];
    const float* b_hh  = (const float*)d_in[5];
    const float* W_out = (const float*)d_in[6];
    const float* b_out = (const float*)d_in[7];
    float* y = (float*)d_out;

    cudaFuncSetAttribute(step_kernel,
                         cudaFuncAttributeMaxDynamicSharedMemorySize, STEP_SMEM);

    q_kernel<<<VOCAB, 256>>>(emb, W_ih, b_ih, b_hh);
    t0_kernel<<<BATCH, 128>>>(ids);
    for (int t = 1; t < SEQ; t++)
        step_kernel<<<dim3(HDIM / 64, BATCH / 128), 256, STEP_SMEM>>>(W_hh, ids, t);
    y_kernel<<<(BATCH * SEQ) / 256, 256>>>(W_out, b_out, y);
}